// round 11
// baseline (speedup 1.0000x reference)
#include <cuda_runtime.h>
#include <cstdint>

#define B_ 2
#define L_ 384
#define H_ 256
#define A_ 14
#define BL (B_ * L_)      // 768
#define IT 4              // i's per block
#define NIG (BL / IT)     // 192 i-groups
#define NJT 3             // j-tiles of 128
#define JTL 128

// ---------------- scratch (static device globals; no allocations) ----------------
__device__ float g_hw[BL * H_];     // [bi][h]
__device__ float g_hu[BL * H_];     // [bj][h]
__device__ float g_S[BL * A_ * 4];  // [bi][a][q]: q<3 -> sum gate*m*Xj_c ; q==3 -> sum gate*m

// ---------------- helpers ----------------
__device__ __forceinline__ void cp16(uint32_t s, const void* g) {
    asm volatile("cp.async.cg.shared.global [%0], [%1], 16;" :: "r"(s), "l"(g));
}
__device__ __forceinline__ void cp_commit() { asm volatile("cp.async.commit_group;"); }
template<int N> __device__ __forceinline__ void cp_wait() {
    asm volatile("cp.async.wait_group %0;" :: "n"(N));
}
__device__ __forceinline__ uint32_t smem_u32(const void* p) {
    uint32_t a;
    asm("{ .reg .u64 t; cvta.to.shared.u64 t, %1; cvt.u32.u64 %0, t; }" : "=r"(a) : "l"(p));
    return a;
}
__device__ __forceinline__ uint32_t tf32r(float x) {
    uint32_t r;
    asm("cvt.rna.tf32.f32 %0, %1;" : "=r"(r) : "f"(x));
    return r;
}
__device__ __forceinline__ void mma_tf32(float* d, uint32_t a0, uint32_t a1,
                                         uint32_t a2, uint32_t a3,
                                         uint32_t b0, uint32_t b1) {
    asm volatile(
        "mma.sync.aligned.m16n8k8.row.col.f32.tf32.tf32.f32 "
        "{%0,%1,%2,%3}, {%4,%5,%6,%7}, {%8,%9}, {%0,%1,%2,%3};"
        : "+f"(d[0]), "+f"(d[1]), "+f"(d[2]), "+f"(d[3])
        : "r"(a0), "r"(a1), "r"(a2), "r"(a3), "r"(b0), "r"(b1));
}

// ---------------- kernel 1: hw/hu = h@W^T+b (fp32, reg double-buffered) ----------------
__global__ __launch_bounds__(128) void gemm_k(
    const float* __restrict__ h,
    const float* __restrict__ Wx, const float* __restrict__ Wxb,
    const float* __restrict__ Ux, const float* __restrict__ Uxb)
{
    {   // zero partial-sum accumulator (43008 floats over 49152 threads)
        int fb = blockIdx.x + 24 * (blockIdx.y + 8 * blockIdx.z);
        int gtid = fb * 128 + threadIdx.x;
        if (gtid < BL * A_ * 4) g_S[gtid] = 0.f;
    }
    const int z = blockIdx.z;
    const float* W    = z ? Ux  : Wx;
    const float* bias = z ? Uxb : Wxb;
    const int m0 = blockIdx.x * 32;
    const int n0 = blockIdx.y * 32;

    __shared__ float As[16][32];
    __shared__ float Bs[16][32];

    const int tid = threadIdx.x;
    const int tm = tid & 15, tn = tid >> 4;
    const int srow = tid >> 2, skq = (tid & 3) * 4;   // staging coords

    float acc[2][4] = {};

    // prefetch chunk 0
    float4 pa = *(const float4*)&h[(m0 + srow) * H_ + skq];
    float4 pb = *(const float4*)&W[(n0 + srow) * H_ + skq];

    for (int k0 = 0; k0 < H_; k0 += 16) {
        As[skq + 0][srow] = pa.x; As[skq + 1][srow] = pa.y;
        As[skq + 2][srow] = pa.z; As[skq + 3][srow] = pa.w;
        Bs[skq + 0][srow] = pb.x; Bs[skq + 1][srow] = pb.y;
        Bs[skq + 2][srow] = pb.z; Bs[skq + 3][srow] = pb.w;
        __syncthreads();
        if (k0 + 16 < H_) {   // kick off next chunk's loads immediately
            pa = *(const float4*)&h[(m0 + srow) * H_ + k0 + 16 + skq];
            pb = *(const float4*)&W[(n0 + srow) * H_ + k0 + 16 + skq];
        }
        #pragma unroll
        for (int k = 0; k < 16; k++) {
            float2 a2 = *(const float2*)&As[k][tm * 2];
            float4 b4 = *(const float4*)&Bs[k][tn * 4];
            acc[0][0] += a2.x * b4.x; acc[0][1] += a2.x * b4.y;
            acc[0][2] += a2.x * b4.z; acc[0][3] += a2.x * b4.w;
            acc[1][0] += a2.y * b4.x; acc[1][1] += a2.y * b4.y;
            acc[1][2] += a2.y * b4.z; acc[1][3] += a2.y * b4.w;
        }
        __syncthreads();
    }

    #pragma unroll
    for (int r = 0; r < 2; r++) {
        int m = m0 + tm * 2 + r;
        #pragma unroll
        for (int c = 0; c < 4; c++) {
            int n = n0 + tn * 4 + c;
            float val = acc[r][c] + bias[n];
            if (z == 0) g_hw[m * H_ + n] = val;
            else        g_hu[m * H_ + n] = val;
        }
    }
}

// ---------------- kernel 2: tf32 mma.sync pairwise gate + partial fold ----------------
// Block = (i-group of 4) x (j-tile of 128); 256 threads = 8 warps; warp w owns
// j rows [16w, 16w+16) and loops all 4 i's. hu staging is WARP-LOCAL (each warp
// cp.asyncs exactly its own 16 rows) -> no __syncthreads in the main loop.
#define TX_F  (16 * 264)      // tf32-rounded Tx, padded pitch 264 (bank-clean)
#define HW_F  (IT * H_)       // 1024
#define HUP   36              // float pitch per j row in a 32-h chunk
#define HUBUF (JTL * HUP)     // 4608 floats per buffer
#define SMEM_F (TX_F + HW_F + 2 * HUBUF)   // 14464 floats = 57856 B
#define SMEM_BYTES (SMEM_F * 4)

__global__ __launch_bounds__(256) void pair_k(
    const float* __restrict__ X, const int* __restrict__ mask,
    const float* __restrict__ Txw, const float* __restrict__ Txb)
{
    extern __shared__ float smf[];
    uint32_t* tx  = (uint32_t*)smf;            // [16][264] tf32 bits (rows 14,15 zero)
    float*    hws = smf + TX_F;                // [4][256]
    float*    hub = smf + TX_F + HW_F;         // 2 x [128][36]
    float*    xm  = hub;                       // overlay after MMA: [128][14][4]
    __shared__ float txbs[16];

    const int t = threadIdx.x, w = t >> 5, lane = t & 31;
    const int g = lane >> 2, c = lane & 3;
    const int ig = blockIdx.x, jt = blockIdx.y;
    const int ibase = ig * IT;
    const int b  = ibase / L_;
    const int j0 = jt * JTL;

    const uint32_t hub0 = smem_u32(hub);
    const float* hus = g_hu + (size_t)(b * L_ + j0) * H_;

    // warp-local staging coords: warp w stages rows [16w, 16w+16).
    // lane pair (2k, 2k+1) covers adjacent 16B chunks -> 32B-coalesced.
    const int st_r = 16 * w + (lane >> 1);   // this lane's row
    const int st_b = lane & 1;               // col parity

    // stage hu chunk 0 (own rows): 4 cp16/lane
    {
        const float* src = hus + st_r * H_;
        uint32_t dst = hub0 + (uint32_t)(st_r * HUP) * 4;
        #pragma unroll
        for (int q = 0; q < 4; q++) {
            int c8 = st_b + 2 * q;    // 16B-chunk index 0..7
            cp16(dst + (uint32_t)(c8 * 16), src + c8 * 4);
        }
        cp_commit();
    }
    // stage Tx (tf32-rounded), txb, hw
    for (int idx = t; idx < 16 * H_; idx += 256) {
        int a = idx >> 8, hh = idx & 255;
        float v = (a < A_) ? Txw[a * H_ + hh] : 0.f;
        tx[a * 264 + hh] = tf32r(v);
    }
    if (t < 16) txbs[t] = (t < A_) ? Txb[t] : 0.f;
    for (int idx = t; idx < IT * H_; idx += 256)
        hws[idx] = g_hw[ibase * H_ + idx];

    float acc[IT][2][4];
    #pragma unroll
    for (int i = 0; i < IT; i++)
        #pragma unroll
        for (int n = 0; n < 2; n++)
            #pragma unroll
            for (int r = 0; r < 4; r++) acc[i][n][r] = 0.f;

    const int jr0 = w * 16 + g, jr1 = jr0 + 8;

    __syncthreads();   // tx/hws visible to all warps (hu is warp-local)

    for (int kc = 0; kc < 8; kc++) {
        if (kc < 7) {   // stage next chunk (own rows) into other buffer
            uint32_t dst = hub0 + (uint32_t)(((kc + 1) & 1) * HUBUF + st_r * HUP) * 4;
            const float* src = hus + st_r * H_ + (kc + 1) * 32;
            #pragma unroll
            for (int q = 0; q < 4; q++) {
                int c8 = st_b + 2 * q;
                cp16(dst + (uint32_t)(c8 * 16), src + c8 * 4);
            }
            cp_commit();
            cp_wait<1>();   // our chunk-kc rows are in
        } else {
            cp_wait<0>();
        }

        const float* hb = hub + (kc & 1) * HUBUF;
        #pragma unroll
        for (int ks = 0; ks < 4; ks++) {
            const int kk = kc * 32 + ks * 8;   // global h base of this k8
            const int kl = ks * 8;             // within-chunk base
            uint32_t b00 = tx[g * 264 + kk + c];
            uint32_t b01 = tx[g * 264 + kk + c + 4];
            uint32_t b10 = tx[(g + 8) * 264 + kk + c];
            uint32_t b11 = tx[(g + 8) * 264 + kk + c + 4];
            float h0c  = hb[jr0 * HUP + kl + c];
            float h1c  = hb[jr1 * HUP + kl + c];
            float h0c4 = hb[jr0 * HUP + kl + c + 4];
            float h1c4 = hb[jr1 * HUP + kl + c + 4];
            #pragma unroll
            for (int i = 0; i < IT; i++) {
                float wc  = hws[i * H_ + kk + c];       // broadcast
                float wc4 = hws[i * H_ + kk + c + 4];
                uint32_t a0 = tf32r(fmaxf(h0c  + wc,  0.f));
                uint32_t a1 = tf32r(fmaxf(h1c  + wc,  0.f));
                uint32_t a2 = tf32r(fmaxf(h0c4 + wc4, 0.f));
                uint32_t a3 = tf32r(fmaxf(h1c4 + wc4, 0.f));
                mma_tf32(acc[i][0], a0, a1, a2, a3, b00, b01);
                mma_tf32(acc[i][1], a0, a1, a2, a3, b10, b11);
            }
        }
    }

    __syncthreads();   // all warps done with hub before xm overlay

    // ---- overlay xm = {X*m (q<3), m} onto hu region ----
    for (int idx = t; idx < JTL * A_; idx += 256) {
        int j = idx / A_, a = idx % A_;
        float m = (float)mask[b * L_ + j0 + j];
        const float* xp = X + ((size_t)(b * L_ + j0 + j) * A_ + a) * 3;
        float* d = xm + idx * 4;
        d[0] = xp[0] * m; d[1] = xp[1] * m; d[2] = xp[2] * m; d[3] = m;
    }
    __syncthreads();

    // ---- fold: gate -> per-(a,q) partials, shuffle-reduce over g, atomicAdd ----
    const float tb[4] = { txbs[2 * c], txbs[2 * c + 1], txbs[8 + 2 * c], txbs[9 + 2 * c] };
    #pragma unroll
    for (int i = 0; i < IT; i++) {
        float f[4][4];
        #pragma unroll
        for (int s = 0; s < 4; s++)
            #pragma unroll
            for (int q = 0; q < 4; q++) f[s][q] = 0.f;

        #pragma unroll
        for (int n = 0; n < 2; n++) {
            int an = n * 8 + 2 * c;
            #pragma unroll
            for (int r = 0; r < 4; r++) {
                int jr = (r >> 1) ? jr1 : jr0;
                int a  = an + (r & 1);
                int s  = n * 2 + (r & 1);
                float v = acc[i][n][r] + tb[s];
                const float* xp = xm + (jr * A_ + a) * 4;  // a=14,15 stray (guarded below)
                float4 x4 = *(const float4*)xp;
                f[s][0] += v * x4.x; f[s][1] += v * x4.y;
                f[s][2] += v * x4.z; f[s][3] += v * x4.w;
            }
        }
        #pragma unroll
        for (int s = 0; s < 4; s++)
            #pragma unroll
            for (int q = 0; q < 4; q++) {
                float v = f[s][q];
                v += __shfl_xor_sync(0xffffffffu, v, 4);
                v += __shfl_xor_sync(0xffffffffu, v, 8);
                v += __shfl_xor_sync(0xffffffffu, v, 16);
                f[s][q] = v;
            }
        if (lane < 4) {   // lane == c
            #pragma unroll
            for (int s = 0; s < 4; s++) {
                int a = (s >> 1) * 8 + 2 * lane + (s & 1);
                if (a < A_) {
                    #pragma unroll
                    for (int q = 0; q < 4; q++)
                        atomicAdd(&g_S[((ibase + i) * A_ + a) * 4 + q], f[s][q]);
                }
            }
        }
    }
}

// ---------------- kernel 3: finalize ----------------
__global__ void fin_k(const float* __restrict__ X, const int* __restrict__ mask,
                      float* __restrict__ out)
{
    const int bi = blockIdx.x, t = threadIdx.x;
    const int b = bi / L_;
    __shared__ float smv[64];
    float s = 0.f;
    for (int j = t; j < L_; j += 64) s += (float)mask[b * L_ + j];
    smv[t] = s;
    __syncthreads();
    if (t == 0) {
        float tot = 0.f;
        for (int k = 0; k < 64; k++) tot += smv[k];
        smv[0] = tot;
    }
    __syncthreads();
    if (t < A_ * 3) {
        int a = t / 3, c = t % 3;
        float S = g_S[(bi * A_ + a) * 4 + c];
        float G = g_S[(bi * A_ + a) * 4 + 3];
        float Xi = X[((size_t)bi * A_ + a) * 3 + c];
        float f = (Xi * G - S) / (1e-6f + smv[0]);
        f = fminf(fmaxf(f, -20.f), 20.f);
        out[((size_t)bi * A_ + a) * 3 + c] = Xi + f;
    }
}

// ---------------- launch ----------------
extern "C" void kernel_launch(void* const* d_in, const int* in_sizes, int n_in,
                              void* d_out, int out_size) {
    const float* h    = (const float*)d_in[0];
    const float* X    = (const float*)d_in[1];
    const int*   mask = (const int*)  d_in[2];
    const float* Wxw  = (const float*)d_in[3];
    const float* Wxb  = (const float*)d_in[4];
    const float* Uxw  = (const float*)d_in[5];
    const float* Uxb  = (const float*)d_in[6];
    const float* Txw  = (const float*)d_in[7];
    const float* Txb  = (const float*)d_in[8];
    float* out = (float*)d_out;

    cudaFuncSetAttribute(pair_k, cudaFuncAttributeMaxDynamicSharedMemorySize, SMEM_BYTES);

    gemm_k<<<dim3(24, 8, 2), 128>>>(h, Wxw, Wxb, Uxw, Uxb);
    pair_k<<<dim3(NIG, NJT), 256, SMEM_BYTES>>>(X, mask, Txw, Txb);
    fin_k<<<BL, 64>>>(X, mask, out);
}

// round 12
// speedup vs baseline: 1.4966x; 1.4966x over previous
#include <cuda_runtime.h>
#include <cstdint>

#define B_ 2
#define L_ 384
#define H_ 256
#define A_ 14
#define BL (B_ * L_)      // 768
#define IT 4              // i's per block
#define NIG (BL / IT)     // 192 i-groups
#define NJT 3             // j-tiles of 128
#define JTL 128

// ---------------- scratch (static device globals; no allocations) ----------------
__device__ float g_hw[BL * H_];     // [bi][h]
__device__ float g_hu[BL * H_];     // [bj][h]
__device__ float g_S[BL * A_ * 4];  // [bi][a][q]: q<3 -> sum gate*m*Xj_c ; q==3 -> sum gate*m

// ---------------- helpers ----------------
__device__ __forceinline__ void cp16(uint32_t s, const void* g) {
    asm volatile("cp.async.cg.shared.global [%0], [%1], 16;" :: "r"(s), "l"(g));
}
__device__ __forceinline__ void cp_commit() { asm volatile("cp.async.commit_group;"); }
template<int N> __device__ __forceinline__ void cp_wait() {
    asm volatile("cp.async.wait_group %0;" :: "n"(N));
}
__device__ __forceinline__ uint32_t smem_u32(const void* p) {
    uint32_t a;
    asm("{ .reg .u64 t; cvta.to.shared.u64 t, %1; cvt.u32.u64 %0, t; }" : "=r"(a) : "l"(p));
    return a;
}
__device__ __forceinline__ uint32_t tf32r(float x) {
    uint32_t r;
    asm("cvt.rna.tf32.f32 %0, %1;" : "=r"(r) : "f"(x));
    return r;
}
__device__ __forceinline__ void mma_tf32(float* d, uint32_t a0, uint32_t a1,
                                         uint32_t a2, uint32_t a3,
                                         uint32_t b0, uint32_t b1) {
    asm volatile(
        "mma.sync.aligned.m16n8k8.row.col.f32.tf32.tf32.f32 "
        "{%0,%1,%2,%3}, {%4,%5,%6,%7}, {%8,%9}, {%0,%1,%2,%3};"
        : "+f"(d[0]), "+f"(d[1]), "+f"(d[2]), "+f"(d[3])
        : "r"(a0), "r"(a1), "r"(a2), "r"(a3), "r"(b0), "r"(b1));
}

// ---------------- kernel 1: hw/hu = h@W^T+b ----------------
// 32x32 tile, 256 threads (2x2 micro-tile), K-chunks of 32 double-buffered,
// ONE __syncthreads per chunk (the iter-start sync orders all reads of the
// buffer this iter's STS overwrites).
#define GKC 32
__global__ __launch_bounds__(256) void gemm_k(
    const float* __restrict__ h,
    const float* __restrict__ Wx, const float* __restrict__ Wxb,
    const float* __restrict__ Ux, const float* __restrict__ Uxb)
{
    {   // zero partial-sum accumulator (43008 floats over 98304 threads)
        int fb = blockIdx.x + 24 * (blockIdx.y + 8 * blockIdx.z);
        int gtid = fb * 256 + threadIdx.x;
        if (gtid < BL * A_ * 4) g_S[gtid] = 0.f;
    }
    const int z = blockIdx.z;
    const float* W    = z ? Ux  : Wx;
    const float* bias = z ? Uxb : Wxb;
    const int m0 = blockIdx.x * 32;
    const int n0 = blockIdx.y * 32;

    __shared__ float As[2][GKC][32];   // [buf][k][m]
    __shared__ float Bs[2][GKC][32];   // [buf][k][n]

    const int t = threadIdx.x;
    const int tm = t & 15, tn = t >> 4;
    const int srow = t >> 3, skq = (t & 7) * 4;   // staging: 32 rows x 32 k per chunk

    float acc[2][2] = {};

    // prologue: load + store chunk 0
    float4 pa = *(const float4*)&h[(m0 + srow) * H_ + skq];
    float4 pb = *(const float4*)&W[(n0 + srow) * H_ + skq];
    As[0][skq + 0][srow] = pa.x; As[0][skq + 1][srow] = pa.y;
    As[0][skq + 2][srow] = pa.z; As[0][skq + 3][srow] = pa.w;
    Bs[0][skq + 0][srow] = pb.x; Bs[0][skq + 1][srow] = pb.y;
    Bs[0][skq + 2][srow] = pb.z; Bs[0][skq + 3][srow] = pb.w;

    #pragma unroll
    for (int kc = 0; kc < H_ / GKC; kc++) {
        __syncthreads();   // buf[kc&1] ready; all reads of buf[(kc+1)&1] (iter kc-1) done
        if (kc + 1 < H_ / GKC) {   // overlap next chunk's LDG with compute
            pa = *(const float4*)&h[(m0 + srow) * H_ + (kc + 1) * GKC + skq];
            pb = *(const float4*)&W[(n0 + srow) * H_ + (kc + 1) * GKC + skq];
        }
        const int cb = kc & 1;
        #pragma unroll
        for (int k = 0; k < GKC; k++) {
            float2 a2 = *(const float2*)&As[cb][k][tm * 2];
            float2 b2 = *(const float2*)&Bs[cb][k][tn * 2];
            acc[0][0] += a2.x * b2.x; acc[0][1] += a2.x * b2.y;
            acc[1][0] += a2.y * b2.x; acc[1][1] += a2.y * b2.y;
        }
        if (kc + 1 < H_ / GKC) {
            const int nb = (kc + 1) & 1;
            As[nb][skq + 0][srow] = pa.x; As[nb][skq + 1][srow] = pa.y;
            As[nb][skq + 2][srow] = pa.z; As[nb][skq + 3][srow] = pa.w;
            Bs[nb][skq + 0][srow] = pb.x; Bs[nb][skq + 1][srow] = pb.y;
            Bs[nb][skq + 2][srow] = pb.z; Bs[nb][skq + 3][srow] = pb.w;
        }
    }

    #pragma unroll
    for (int r = 0; r < 2; r++) {
        int m = m0 + tm * 2 + r;
        int n = n0 + tn * 2;
        float2 v = make_float2(acc[r][0] + bias[n], acc[r][1] + bias[n + 1]);
        if (z == 0) *(float2*)&g_hw[m * H_ + n] = v;
        else        *(float2*)&g_hu[m * H_ + n] = v;
    }
}

// ---------------- kernel 2: tf32 mma.sync pairwise gate + partial fold ----------------
// (exact R10 configuration — known-good 64.3us path)
#define TX_F  (16 * 264)      // tf32-rounded Tx, padded pitch 264 (bank-clean)
#define HW_F  (IT * H_)       // 1024
#define HUP   36              // float pitch per j row in a 32-h chunk
#define HUBUF (JTL * HUP)     // 4608 floats per buffer
#define SMEM_F (TX_F + HW_F + 2 * HUBUF)   // 14464 floats = 57856 B
#define SMEM_BYTES (SMEM_F * 4)

__global__ __launch_bounds__(256) void pair_k(
    const float* __restrict__ X, const int* __restrict__ mask,
    const float* __restrict__ Txw, const float* __restrict__ Txb)
{
    extern __shared__ float smf[];
    uint32_t* tx  = (uint32_t*)smf;            // [16][264] tf32 bits (rows 14,15 zero)
    float*    hws = smf + TX_F;                // [4][256]
    float*    hub = smf + TX_F + HW_F;         // 2 x [128][36]
    float*    xm  = hub;                       // overlay after MMA: [128][14][4]
    __shared__ float txbs[16];

    const int t = threadIdx.x, w = t >> 5, lane = t & 31;
    const int g = lane >> 2, c = lane & 3;
    const int ig = blockIdx.x, jt = blockIdx.y;
    const int ibase = ig * IT;
    const int b  = ibase / L_;
    const int j0 = jt * JTL;

    const uint32_t hub0 = smem_u32(hub);
    const float* hus = g_hu + (size_t)(b * L_ + j0) * H_;

    // stage hu chunk 0 (128 j x 32 h): 1024 cp16, 8 lanes per 128B row-segment
    {
        #pragma unroll
        for (int q = 0; q < 4; q++) {
            int idx = t + q * 256, r = idx >> 3, c8 = idx & 7;
            cp16(hub0 + (uint32_t)(r * HUP + c8 * 4) * 4, hus + r * H_ + c8 * 4);
        }
        cp_commit();
    }
    // stage Tx (tf32-rounded), txb, hw
    for (int idx = t; idx < 16 * H_; idx += 256) {
        int a = idx >> 8, hh = idx & 255;
        float v = (a < A_) ? Txw[a * H_ + hh] : 0.f;
        tx[a * 264 + hh] = tf32r(v);
    }
    if (t < 16) txbs[t] = (t < A_) ? Txb[t] : 0.f;
    for (int idx = t; idx < IT * H_; idx += 256)
        hws[idx] = g_hw[ibase * H_ + idx];

    float acc[IT][2][4];
    #pragma unroll
    for (int i = 0; i < IT; i++)
        #pragma unroll
        for (int n = 0; n < 2; n++)
            #pragma unroll
            for (int r = 0; r < 4; r++) acc[i][n][r] = 0.f;

    const int jr0 = w * 16 + g, jr1 = jr0 + 8;

    for (int kc = 0; kc < 8; kc++) {
        if (kc < 7) {   // stage next chunk into other buffer
            uint32_t dst = hub0 + (uint32_t)(((kc + 1) & 1) * HUBUF) * 4;
            const float* src = hus + (kc + 1) * 32;
            #pragma unroll
            for (int q = 0; q < 4; q++) {
                int idx = t + q * 256, r = idx >> 3, c8 = idx & 7;
                cp16(dst + (uint32_t)(r * HUP + c8 * 4) * 4, src + r * H_ + c8 * 4);
            }
            cp_commit();
            cp_wait<1>();
        } else {
            cp_wait<0>();
        }
        __syncthreads();   // chunk kc fully staged (covers prologue at kc=0)

        const float* hb = hub + (kc & 1) * HUBUF;
        #pragma unroll
        for (int ks = 0; ks < 4; ks++) {
            const int kk = kc * 32 + ks * 8;   // global h base of this k8
            const int kl = ks * 8;             // within-chunk base
            uint32_t b00 = tx[g * 264 + kk + c];
            uint32_t b01 = tx[g * 264 + kk + c + 4];
            uint32_t b10 = tx[(g + 8) * 264 + kk + c];
            uint32_t b11 = tx[(g + 8) * 264 + kk + c + 4];
            float h0c  = hb[jr0 * HUP + kl + c];
            float h1c  = hb[jr1 * HUP + kl + c];
            float h0c4 = hb[jr0 * HUP + kl + c + 4];
            float h1c4 = hb[jr1 * HUP + kl + c + 4];
            #pragma unroll
            for (int i = 0; i < IT; i++) {
                float wc  = hws[i * H_ + kk + c];       // broadcast
                float wc4 = hws[i * H_ + kk + c + 4];
                uint32_t a0 = tf32r(fmaxf(h0c  + wc,  0.f));
                uint32_t a1 = tf32r(fmaxf(h1c  + wc,  0.f));
                uint32_t a2 = tf32r(fmaxf(h0c4 + wc4, 0.f));
                uint32_t a3 = tf32r(fmaxf(h1c4 + wc4, 0.f));
                mma_tf32(acc[i][0], a0, a1, a2, a3, b00, b01);
                mma_tf32(acc[i][1], a0, a1, a2, a3, b10, b11);
            }
        }
        __syncthreads();   // all reads of this buffer done before restage
    }

    // ---- overlay xm = {X*m (q<3), m} onto hu region ----
    for (int idx = t; idx < JTL * A_; idx += 256) {
        int j = idx / A_, a = idx % A_;
        float m = (float)mask[b * L_ + j0 + j];
        const float* xp = X + ((size_t)(b * L_ + j0 + j) * A_ + a) * 3;
        float* d = xm + idx * 4;
        d[0] = xp[0] * m; d[1] = xp[1] * m; d[2] = xp[2] * m; d[3] = m;
    }
    __syncthreads();

    // ---- fold: gate -> per-(a,q) partials, shuffle-reduce over g, atomicAdd ----
    const float tb[4] = { txbs[2 * c], txbs[2 * c + 1], txbs[8 + 2 * c], txbs[9 + 2 * c] };
    #pragma unroll
    for (int i = 0; i < IT; i++) {
        float f[4][4];
        #pragma unroll
        for (int s = 0; s < 4; s++)
            #pragma unroll
            for (int q = 0; q < 4; q++) f[s][q] = 0.f;

        #pragma unroll
        for (int n = 0; n < 2; n++) {
            int an = n * 8 + 2 * c;
            #pragma unroll
            for (int r = 0; r < 4; r++) {
                int jr = (r >> 1) ? jr1 : jr0;
                int a  = an + (r & 1);
                int s  = n * 2 + (r & 1);
                float v = acc[i][n][r] + tb[s];
                const float* xp = xm + (jr * A_ + a) * 4;  // a=14,15 stray (guarded below)
                float4 x4 = *(const float4*)xp;
                f[s][0] += v * x4.x; f[s][1] += v * x4.y;
                f[s][2] += v * x4.z; f[s][3] += v * x4.w;
            }
        }
        #pragma unroll
        for (int s = 0; s < 4; s++)
            #pragma unroll
            for (int q = 0; q < 4; q++) {
                float v = f[s][q];
                v += __shfl_xor_sync(0xffffffffu, v, 4);
                v += __shfl_xor_sync(0xffffffffu, v, 8);
                v += __shfl_xor_sync(0xffffffffu, v, 16);
                f[s][q] = v;
            }
        if (lane < 4) {   // lane == c
            #pragma unroll
            for (int s = 0; s < 4; s++) {
                int a = (s >> 1) * 8 + 2 * lane + (s & 1);
                if (a < A_) {
                    #pragma unroll
                    for (int q = 0; q < 4; q++)
                        atomicAdd(&g_S[((ibase + i) * A_ + a) * 4 + q], f[s][q]);
                }
            }
        }
    }
}

// ---------------- kernel 3: finalize ----------------
__global__ void fin_k(const float* __restrict__ X, const int* __restrict__ mask,
                      float* __restrict__ out)
{
    const int bi = blockIdx.x, t = threadIdx.x;
    const int b = bi / L_;
    __shared__ float smv[64];
    float s = 0.f;
    for (int j = t; j < L_; j += 64) s += (float)mask[b * L_ + j];
    smv[t] = s;
    __syncthreads();
    if (t == 0) {
        float tot = 0.f;
        for (int k = 0; k < 64; k++) tot += smv[k];
        smv[0] = tot;
    }
    __syncthreads();
    if (t < A_ * 3) {
        int a = t / 3, c = t % 3;
        float S = g_S[(bi * A_ + a) * 4 + c];
        float G = g_S[(bi * A_ + a) * 4 + 3];
        float Xi = X[((size_t)bi * A_ + a) * 3 + c];
        float f = (Xi * G - S) / (1e-6f + smv[0]);
        f = fminf(fmaxf(f, -20.f), 20.f);
        out[((size_t)bi * A_ + a) * 3 + c] = Xi + f;
    }
}

// ---------------- launch ----------------
extern "C" void kernel_launch(void* const* d_in, const int* in_sizes, int n_in,
                              void* d_out, int out_size) {
    const float* h    = (const float*)d_in[0];
    const float* X    = (const float*)d_in[1];
    const int*   mask = (const int*)  d_in[2];
    const float* Wxw  = (const float*)d_in[3];
    const float* Wxb  = (const float*)d_in[4];
    const float* Uxw  = (const float*)d_in[5];
    const float* Uxb  = (const float*)d_in[6];
    const float* Txw  = (const float*)d_in[7];
    const float* Txb  = (const float*)d_in[8];
    float* out = (float*)d_out;

    cudaFuncSetAttribute(pair_k, cudaFuncAttributeMaxDynamicSharedMemorySize, SMEM_BYTES);

    gemm_k<<<dim3(24, 8, 2), 256>>>(h, Wxw, Wxb, Uxw, Uxb);
    pair_k<<<dim3(NIG, NJT), 256, SMEM_BYTES>>>(X, mask, Txw, Txb);
    fin_k<<<BL, 64>>>(X, mask, out);
}

// round 15
// speedup vs baseline: 2.0163x; 1.3473x over previous
#include <cuda_runtime.h>
#include <cstdint>

#define B_ 2
#define L_ 384
#define H_ 256
#define A_ 14
#define BL (B_ * L_)      // 768
#define IT 4              // i's per block
#define NIG (BL / IT)     // 192 i-groups
#define NJT 3             // j-tiles of 128
#define JTL 128
#define H2 (H_ / 2)       // 128 packed half2 per row

// ---------------- scratch (static device globals; no allocations) ----------------
// hw/hu stored as packed f16x2 (two adjacent h per u32)
__device__ __align__(16) uint32_t g_hwh[BL * H2];
__device__ __align__(16) uint32_t g_huh[BL * H2];
__device__ float g_S[BL * A_ * 4];  // [bi][a][q]: q<3 -> sum gate*m*Xj_c ; q==3 -> sum gate*m

// ---------------- helpers ----------------
__device__ __forceinline__ void cp16(uint32_t s, const void* g) {
    asm volatile("cp.async.cg.shared.global [%0], [%1], 16;" :: "r"(s), "l"(g));
}
__device__ __forceinline__ void cp_commit() { asm volatile("cp.async.commit_group;"); }
template<int N> __device__ __forceinline__ void cp_wait() {
    asm volatile("cp.async.wait_group %0;" :: "n"(N));
}
__device__ __forceinline__ uint32_t smem_u32(const void* p) {
    uint32_t a;
    asm("{ .reg .u64 t; cvta.to.shared.u64 t, %1; cvt.u32.u64 %0, t; }" : "=r"(a) : "l"(p));
    return a;
}
// pack {lo, hi} floats -> f16x2 (lo in low 16 bits)
__device__ __forceinline__ uint32_t f2h2(float lo, float hi) {
    uint32_t r;
    asm("cvt.rn.f16x2.f32 %0, %1, %2;" : "=r"(r) : "f"(hi), "f"(lo));
    return r;
}
// relu(a + b) on packed f16x2
__device__ __forceinline__ uint32_t hadd2max0(uint32_t a, uint32_t b) {
    uint32_t r;
    asm("{ .reg .b32 s; add.f16x2 s, %1, %2; max.f16x2 %0, s, %3; }"
        : "=r"(r) : "r"(a), "r"(b), "r"(0u));
    return r;
}
__device__ __forceinline__ void mma_f16(float* d, uint32_t a0, uint32_t a1,
                                        uint32_t a2, uint32_t a3,
                                        uint32_t b0, uint32_t b1) {
    asm volatile(
        "mma.sync.aligned.m16n8k16.row.col.f32.f16.f16.f32 "
        "{%0,%1,%2,%3}, {%4,%5,%6,%7}, {%8,%9}, {%0,%1,%2,%3};"
        : "+f"(d[0]), "+f"(d[1]), "+f"(d[2]), "+f"(d[3])
        : "r"(a0), "r"(a1), "r"(a2), "r"(a3), "r"(b0), "r"(b1));
}

// ---------------- kernel 1: hw/hu = h@W^T+b -> packed f16x2 (R10 structure) ----------------
__global__ __launch_bounds__(128) void gemm_k(
    const float* __restrict__ h,
    const float* __restrict__ Wx, const float* __restrict__ Wxb,
    const float* __restrict__ Ux, const float* __restrict__ Uxb)
{
    {   // zero partial-sum accumulator (43008 floats over 49152 threads)
        int fb = blockIdx.x + 24 * (blockIdx.y + 8 * blockIdx.z);
        int gtid = fb * 128 + threadIdx.x;
        if (gtid < BL * A_ * 4) g_S[gtid] = 0.f;
    }
    const int z = blockIdx.z;
    const float* W    = z ? Ux  : Wx;
    const float* bias = z ? Uxb : Wxb;
    const int m0 = blockIdx.x * 32;
    const int n0 = blockIdx.y * 32;

    __shared__ float As[16][32];
    __shared__ float Bs[16][32];

    const int tid = threadIdx.x;
    const int tm = tid & 15, tn = tid >> 4;

    float acc[2][4] = {};

    for (int k0 = 0; k0 < H_; k0 += 16) {
        {
            int row = tid >> 2, kq = (tid & 3) * 4;
            float4 a = *(const float4*)&h[(m0 + row) * H_ + k0 + kq];
            As[kq + 0][row] = a.x; As[kq + 1][row] = a.y;
            As[kq + 2][row] = a.z; As[kq + 3][row] = a.w;
            float4 bv = *(const float4*)&W[(n0 + row) * H_ + k0 + kq];
            Bs[kq + 0][row] = bv.x; Bs[kq + 1][row] = bv.y;
            Bs[kq + 2][row] = bv.z; Bs[kq + 3][row] = bv.w;
        }
        __syncthreads();
        #pragma unroll
        for (int k = 0; k < 16; k++) {
            float2 a2 = *(const float2*)&As[k][tm * 2];
            float4 b4 = *(const float4*)&Bs[k][tn * 4];
            acc[0][0] += a2.x * b4.x; acc[0][1] += a2.x * b4.y;
            acc[0][2] += a2.x * b4.z; acc[0][3] += a2.x * b4.w;
            acc[1][0] += a2.y * b4.x; acc[1][1] += a2.y * b4.y;
            acc[1][2] += a2.y * b4.z; acc[1][3] += a2.y * b4.w;
        }
        __syncthreads();
    }

    #pragma unroll
    for (int r = 0; r < 2; r++) {
        int m = m0 + tm * 2 + r;
        int n = n0 + tn * 4;
        uint32_t v0 = f2h2(acc[r][0] + bias[n],     acc[r][1] + bias[n + 1]);
        uint32_t v1 = f2h2(acc[r][2] + bias[n + 2], acc[r][3] + bias[n + 3]);
        uint32_t* dst = (z ? g_huh : g_hwh) + m * H2 + (n >> 1);
        dst[0] = v0; dst[1] = v1;
    }
}

// ---------------- kernel 2: f16 mma.sync pairwise gate + partial fold ----------------
// Block = (i-group of 4) x (j-tile of 128); 256 threads = 8 warps; warp w owns
// j rows [16w, 16w+16), loops 4 i's. A = relu(hw+hu) built as packed f16x2.
#define TX2_U  (16 * 132)     // [16 a][132] u32 (h2-pitch 132 == 4 mod 32: bank-clean)
#define HW2_U  (IT * H2)      // 512 u32
#define HUP2   20             // u32 pitch per j row per 32-h chunk (16 data + 4 pad)
#define HUBUF2 (JTL * HUP2)   // 2560 u32 per buffer
#define SMEM_U (TX2_U + HW2_U + 2 * HUBUF2)   // 7744 u32 = 30976 B
#define SMEM_BYTES (SMEM_U * 4)
// xm overlay (after MMA): 128*14*4 floats = 28672 B <= 30976 B  ✓

__global__ __launch_bounds__(256) void pair_k(
    const float* __restrict__ X, const int* __restrict__ mask,
    const float* __restrict__ Txw, const float* __restrict__ Txb)
{
    extern __shared__ float smf[];
    uint32_t* tx2 = (uint32_t*)smf;            // [16][132] f16x2 Tx (rows 14,15 zero)
    uint32_t* hw2 = tx2 + TX2_U;               // [4][128]
    uint32_t* hub = hw2 + HW2_U;               // 2 x [128][20]
    float*    xm  = smf;                       // overlay after MMA: [128][14][4]
    __shared__ float txbs[16];

    const int t = threadIdx.x, w = t >> 5, lane = t & 31;
    const int g = lane >> 2, c = lane & 3;
    const int ig = blockIdx.x, jt = blockIdx.y;
    const int ibase = ig * IT;
    const int b  = ibase / L_;
    const int j0 = jt * JTL;

    const uint32_t hub0 = smem_u32(hub);
    const uint32_t* hus = g_huh + (size_t)(b * L_ + j0) * H2;

    // stage hu chunk 0 (128 j x 16 u32): 512 cp16, 4 lanes per 64B row
    {
        #pragma unroll
        for (int q = 0; q < 2; q++) {
            int idx = t + q * 256, r = idx >> 2, c4 = idx & 3;
            cp16(hub0 + (uint32_t)(r * HUP2 + c4 * 4) * 4, hus + r * H2 + c4 * 4);
        }
        cp_commit();
    }
    // stage Tx (f16x2-packed), txb, hw
    for (int idx = t; idx < 16 * H2; idx += 256) {
        int a = idx >> 7, h2 = idx & 127;
        uint32_t v = 0u;
        if (a < A_) v = f2h2(Txw[a * H_ + 2 * h2], Txw[a * H_ + 2 * h2 + 1]);
        tx2[a * 132 + h2] = v;
    }
    if (t < 16) txbs[t] = (t < A_) ? Txb[t] : 0.f;
    for (int idx = t; idx < IT * H2; idx += 256)
        hw2[idx] = g_hwh[ibase * H2 + idx];

    float acc[IT][2][4];
    #pragma unroll
    for (int i = 0; i < IT; i++)
        #pragma unroll
        for (int n = 0; n < 2; n++)
            #pragma unroll
            for (int r = 0; r < 4; r++) acc[i][n][r] = 0.f;

    const int jr0 = w * 16 + g, jr1 = jr0 + 8;

    for (int kc = 0; kc < 8; kc++) {
        if (kc < 7) {   // stage next chunk into other buffer
            uint32_t dst = hub0 + (uint32_t)(((kc + 1) & 1) * HUBUF2) * 4;
            const uint32_t* src = hus + (kc + 1) * 16;
            #pragma unroll
            for (int q = 0; q < 2; q++) {
                int idx = t + q * 256, r = idx >> 2, c4 = idx & 3;
                cp16(dst + (uint32_t)(r * HUP2 + c4 * 4) * 4, src + r * H2 + c4 * 4);
            }
            cp_commit();
            cp_wait<1>();
        } else {
            cp_wait<0>();
        }
        __syncthreads();   // chunk kc fully staged (covers prologue at kc=0)

        const uint32_t* hb = hub + (kc & 1) * HUBUF2;
        #pragma unroll
        for (int ks = 0; ks < 2; ks++) {
            const int h2b = kc * 16 + ks * 8;   // global h2 base of this k16
            const int kl2 = ks * 8;             // within-chunk u32 base
            uint32_t b00 = tx2[g * 132 + h2b + c];
            uint32_t b01 = tx2[g * 132 + h2b + c + 4];
            uint32_t b10 = tx2[(g + 8) * 132 + h2b + c];
            uint32_t b11 = tx2[(g + 8) * 132 + h2b + c + 4];
            uint32_t h0c  = hb[jr0 * HUP2 + kl2 + c];
            uint32_t h1c  = hb[jr1 * HUP2 + kl2 + c];
            uint32_t h0c4 = hb[jr0 * HUP2 + kl2 + c + 4];
            uint32_t h1c4 = hb[jr1 * HUP2 + kl2 + c + 4];
            #pragma unroll
            for (int i = 0; i < IT; i++) {
                uint32_t wc  = hw2[i * H2 + h2b + c];       // broadcast
                uint32_t wc4 = hw2[i * H2 + h2b + c + 4];
                uint32_t a0 = hadd2max0(h0c,  wc);
                uint32_t a1 = hadd2max0(h1c,  wc);
                uint32_t a2 = hadd2max0(h0c4, wc4);
                uint32_t a3 = hadd2max0(h1c4, wc4);
                mma_f16(acc[i][0], a0, a1, a2, a3, b00, b01);
                mma_f16(acc[i][1], a0, a1, a2, a3, b10, b11);
            }
        }
        __syncthreads();   // all reads of this buffer done before restage
    }

    // ---- overlay xm = {X*m (q<3), m} ----
    for (int idx = t; idx < JTL * A_; idx += 256) {
        int j = idx / A_, a = idx % A_;
        float m = (float)mask[b * L_ + j0 + j];
        const float* xp = X + ((size_t)(b * L_ + j0 + j) * A_ + a) * 3;
        float* d = xm + idx * 4;
        d[0] = xp[0] * m; d[1] = xp[1] * m; d[2] = xp[2] * m; d[3] = m;
    }
    __syncthreads();

    // ---- fold: gate -> per-(a,q) partials, shuffle-reduce over g, atomicAdd ----
    const float tb[4] = { txbs[2 * c], txbs[2 * c + 1], txbs[8 + 2 * c], txbs[9 + 2 * c] };
    #pragma unroll
    for (int i = 0; i < IT; i++) {
        float f[4][4];
        #pragma unroll
        for (int s = 0; s < 4; s++)
            #pragma unroll
            for (int q = 0; q < 4; q++) f[s][q] = 0.f;

        #pragma unroll
        for (int n = 0; n < 2; n++) {
            int an = n * 8 + 2 * c;
            #pragma unroll
            for (int r = 0; r < 4; r++) {
                int jr = (r >> 1) ? jr1 : jr0;
                int a  = an + (r & 1);
                int s  = n * 2 + (r & 1);
                float v = acc[i][n][r] + tb[s];
                const float* xp = xm + (jr * A_ + a) * 4;  // a=14,15 stray (guarded below)
                float4 x4 = *(const float4*)xp;
                f[s][0] += v * x4.x; f[s][1] += v * x4.y;
                f[s][2] += v * x4.z; f[s][3] += v * x4.w;
            }
        }
        #pragma unroll
        for (int s = 0; s < 4; s++)
            #pragma unroll
            for (int q = 0; q < 4; q++) {
                float v = f[s][q];
                v += __shfl_xor_sync(0xffffffffu, v, 4);
                v += __shfl_xor_sync(0xffffffffu, v, 8);
                v += __shfl_xor_sync(0xffffffffu, v, 16);
                f[s][q] = v;
            }
        if (lane < 4) {   // lane == c
            #pragma unroll
            for (int s = 0; s < 4; s++) {
                int a = (s >> 1) * 8 + 2 * lane + (s & 1);
                if (a < A_) {
                    #pragma unroll
                    for (int q = 0; q < 4; q++)
                        atomicAdd(&g_S[((ibase + i) * A_ + a) * 4 + q], f[s][q]);
                }
            }
        }
    }
}

// ---------------- kernel 3: finalize ----------------
__global__ void fin_k(const float* __restrict__ X, const int* __restrict__ mask,
                      float* __restrict__ out)
{
    const int bi = blockIdx.x, t = threadIdx.x;
    const int b = bi / L_;
    __shared__ float smv[64];
    float s = 0.f;
    for (int j = t; j < L_; j += 64) s += (float)mask[b * L_ + j];
    smv[t] = s;
    __syncthreads();
    if (t == 0) {
        float tot = 0.f;
        for (int k = 0; k < 64; k++) tot += smv[k];
        smv[0] = tot;
    }
    __syncthreads();
    if (t < A_ * 3) {
        int a = t / 3, c = t % 3;
        float S = g_S[(bi * A_ + a) * 4 + c];
        float G = g_S[(bi * A_ + a) * 4 + 3];
        float Xi = X[((size_t)bi * A_ + a) * 3 + c];
        float f = (Xi * G - S) / (1e-6f + smv[0]);
        f = fminf(fmaxf(f, -20.f), 20.f);
        out[((size_t)bi * A_ + a) * 3 + c] = Xi + f;
    }
}

// ---------------- launch ----------------
extern "C" void kernel_launch(void* const* d_in, const int* in_sizes, int n_in,
                              void* d_out, int out_size) {
    const float* h    = (const float*)d_in[0];
    const float* X    = (const float*)d_in[1];
    const int*   mask = (const int*)  d_in[2];
    const float* Wxw  = (const float*)d_in[3];
    const float* Wxb  = (const float*)d_in[4];
    const float* Uxw  = (const float*)d_in[5];
    const float* Uxb  = (const float*)d_in[6];
    const float* Txw  = (const float*)d_in[7];
    const float* Txb  = (const float*)d_in[8];
    float* out = (float*)d_out;

    cudaFuncSetAttribute(pair_k, cudaFuncAttributeMaxDynamicSharedMemorySize, SMEM_BYTES);

    gemm_k<<<dim3(24, 8, 2), 128>>>(h, Wxw, Wxb, Uxw, Uxb);
    pair_k<<<dim3(NIG, NJT), 256, SMEM_BYTES>>>(X, mask, Txw, Txb);
    fin_k<<<BL, 64>>>(X, mask, out);
}